// round 14
// baseline (speedup 1.0000x reference)
#include <cuda_runtime.h>
#include <math.h>

// ---------------------------------------------------------------------------
// QECCEqualModel via Givens decomposition (M_k = D1*G*D2):
//   D2 bits 9..12  -> 16-entry phasor table at pass1 load
//   D2 all other   -> one thread-constant rotation at pass1 load
//   G              -> real Givens rotations
//   D1 bits 0..2   -> thread-constant rotation at pass1 store  (ONLY here!)
//   D1 bits 15..18 -> 16-entry packed phasor table in pass2 dot
//   D1 all other   -> single thread-constant end rotation in pass2
// pass1: G on state bits 0..12 via THREE register mappings (2 restages,
//        only ONE shfl gate) -> scratch. Split in two half launches.
// pass2: G on state bits 13..22 (gathered), fused dot with code1.
//        Two per-state launches; p0 overlaps pass1's second half via a
//        forked stream. Last of all 2048 blocks reduces -> loss.
// ---------------------------------------------------------------------------

#define DIMQ (1u << 23)
typedef unsigned long long u64c;

__device__ u64c     g_scratch[2u * DIMQ];
__device__ float    g_partials[2048 * 4];
__device__ unsigned g_count;               // zero-init; reset by last block

__device__ __forceinline__ u64c pk(float x, float y) {
    u64c r; asm("mov.b64 %0,{%1,%2};" : "=l"(r) : "f"(x), "f"(y)); return r;
}
__device__ __forceinline__ void upk(u64c a, float& x, float& y) {
    asm("mov.b64 {%0,%1},%2;" : "=f"(x), "=f"(y) : "l"(a));
}
__device__ __forceinline__ u64c fma2(u64c a, u64c b, u64c c) {
    u64c r; asm("fma.rn.f32x2 %0,%1,%2,%3;" : "=l"(r) : "l"(a), "l"(b), "l"(c)); return r;
}
__device__ __forceinline__ u64c mul2(u64c a, u64c b) {
    u64c r; asm("mul.rn.f32x2 %0,%1,%2;" : "=l"(r) : "l"(a), "l"(b)); return r;
}
// rotate packed complex a by phasor (cs,sn): (x cs - y sn, y cs + x sn)
__device__ __forceinline__ u64c crot(u64c a, u64c CS, u64c SN) {
    float x, y; upk(a, x, y);
    return fma2(pk(-y, x), SN, mul2(a, CS));
}
// rotate by packed phasor (cs,sn) held in one u64
__device__ __forceinline__ u64c crotp(u64c a, u64c P) {
    float cs, sn; upk(P, cs, sn);
    float x, y; upk(a, x, y);
    return fma2(pk(-y, x), pk(sn, sn), mul2(a, pk(cs, cs)));
}

__device__ __forceinline__ unsigned swz4(unsigned i) { return i ^ ((i >> 4) & 0xFu); }

// Per-block Givens decomposition of all 23 gates into smem (threads 0..22).
// M = U^T = [[c e^{ia}, -s e^{i(a+d)}],[s e^{ib}, c e^{i(b+d)}]]
__device__ __forceinline__ void decompose(
    int tid, const float* __restrict__ ur, const float* __restrict__ ui,
    float* s_gc, float* s_gs, float* s_pre, float* s_post)
{
    if (tid < 23) {
        int k = tid;
        float m00r = ur[k*4+0], m00i = ui[k*4+0];
        float m01r = ur[k*4+2], m01i = ui[k*4+2];
        float m10r = ur[k*4+1], m10i = ui[k*4+1];
        float m11r = ur[k*4+3], m11i = ui[k*4+3];
        float c = sqrtf(m00r*m00r + m00i*m00i);
        float s = sqrtf(m10r*m10r + m10i*m10i);
        const float eps = 1e-20f;
        float a = (c > eps) ? atan2f(m00i, m00r) : 0.0f;
        float b = (s > eps) ? atan2f(m10i, m10r) : 0.0f;
        float d = (s > eps) ? (atan2f(-m01i, -m01r) - a)
                            : (atan2f(m11i, m11r) - b);
        int j = 22 - k;            // gate k acts on state bit 22-k
        s_gc[j] = c; s_gs[j] = s;
        s_pre[j] = d; s_post[j] = b - a;
    }
}

// Real Givens across a register bit rb: o0 = c*A0 - s*A1 ; o1 = s*A0 + c*A1
__device__ __forceinline__ void reg_gate_r(u64c (&a)[16], int rb, float c, float s)
{
    u64c cc = pk(c, c), ss = pk(s, s), ns = pk(-s, -s);
#pragma unroll
    for (int r0 = 0; r0 < 16; ++r0) {
        if (r0 & (1 << rb)) continue;
        int r1 = r0 | (1 << rb);
        u64c A0 = a[r0], A1 = a[r1];
        a[r0] = fma2(A1, ns, mul2(A0, cc));
        a[r1] = fma2(A1, cc, mul2(A0, ss));
    }
}

// Real Givens across a lane bit: new = c*me + t*other, t = myb ? s : -s
__device__ __forceinline__ void lane_gate_r(u64c (&a)[16], int mask, int myb,
                                            float c, float s)
{
    float t = myb ? s : -s;
    u64c cc = pk(c, c), tt = pk(t, t);
#pragma unroll
    for (int r = 0; r < 16; ++r) {
        float mx, my; upk(a[r], mx, my);
        float ox = __shfl_xor_sync(0xffffffffu, mx, mask);
        float oy = __shfl_xor_sync(0xffffffffu, my, mask);
        a[r] = fma2(pk(ox, oy), tt, mul2(a[r], cc));
    }
}

// ---------------------------------------------------------------------------
// Pass 1: contiguous tiles of 8192 amps; three mappings, ONE shfl gate.
// m1   t1 = (r<<9)|(w<<5)|lane : lane = tile 0..4, warp = 5..8, reg = 9..12
//        -> gates: reg states 9..12, shfl state 4. Pre-phase at load.
// mmid t  = (w<<9)|(lane<<4)|r : reg = tile 0..3  -> gates states 0..3
// m2   t2 = (w<<9)|(r<<5)|lane : reg = tile 5..8  -> gates states 5..8
//        -> post-phase bits 0..2 (lane-const) + coalesced store.
// Restages use swizzle swz4 (<=2-way conflicts).
// ---------------------------------------------------------------------------
__global__ void __launch_bounds__(512, 2)
pass1_kernel(const float* __restrict__ c0r, const float* __restrict__ c0i,
             const float* __restrict__ ur,  const float* __restrict__ ui,
             unsigned bid0)
{
    __shared__ float s_gc[23], s_gs[23], s_pre[23], s_post[23];
    __shared__ u64c  s_pt[16];     // packed (cs,sn) phasors for pre bits 9..12
    extern __shared__ u64c sm[];   // 8192 u64 = 64 KB restage buffer

    const int tid  = threadIdx.x;
    decompose(tid, ur, ui, s_gc, s_gs, s_pre, s_post);
    __syncthreads();

    if (tid < 16) {
        float ang = 0.0f;
#pragma unroll
        for (int m = 0; m < 4; ++m)
            ang += (float)((tid >> m) & 1) * s_pre[9 + m];
        float sn, cs; __sincosf(ang, &sn, &cs);
        s_pt[tid] = pk(cs, sn);
    }
    __syncthreads();

    const int lane = tid & 31;
    const int w    = tid >> 5;
    const unsigned gbid = blockIdx.x + bid0;
    const unsigned base = gbid * 8192u;

    // thread-constant pre-phase (gbid bits 0..9 = state bits 13..22)
    float th = 0.0f;
#pragma unroll
    for (int m = 0; m < 10; ++m)
        th += (float)((gbid >> m) & 1u) * s_pre[13 + m];
#pragma unroll
    for (int j = 0; j < 5; ++j)
        th += (float)((lane >> j) & 1) * s_pre[j];
#pragma unroll
    for (int m = 0; m < 4; ++m)
        th += (float)((w >> m) & 1) * s_pre[5 + m];
    float snT, csT; __sincosf(th, &snT, &csT);
    const u64c TC = pk(csT, csT), TS = pk(snT, snT);

    u64c a[16];
#pragma unroll
    for (int r = 0; r < 16; ++r) {
        unsigned t1 = (unsigned)(r << 9) | (w << 5) | lane;
        float xr = __ldg(&c0r[base + t1]);
        float xi = __ldg(&c0i[base + t1]);
        u64c x = crotp(pk(xr, xi), s_pt[r]);
        a[r] = crot(x, TC, TS);
    }

    // m1 gates: states 9..12 (reg), state 4 (shfl)
#pragma unroll
    for (int rb = 0; rb < 4; ++rb)
        reg_gate_r(a, rb, s_gc[9 + rb], s_gs[9 + rb]);
    lane_gate_r(a, 1 << 4, (lane >> 4) & 1, s_gc[4], s_gs[4]);

    // restage A: m1 -> mmid
#pragma unroll
    for (int r = 0; r < 16; ++r)
        sm[swz4((unsigned)(r << 9) | (w << 5) | lane)] = a[r];
    __syncthreads();
#pragma unroll
    for (int r = 0; r < 16; ++r)
        a[r] = sm[swz4((unsigned)(w << 9) | (lane << 4) | r)];

    // mmid gates: states 0..3 (reg)
#pragma unroll
    for (int rb = 0; rb < 4; ++rb)
        reg_gate_r(a, rb, s_gc[rb], s_gs[rb]);

    __syncthreads();   // everyone done reading restage A data
    // restage B: mmid -> m2
#pragma unroll
    for (int r = 0; r < 16; ++r)
        sm[swz4((unsigned)(w << 9) | (lane << 4) | r)] = a[r];
    __syncthreads();
#pragma unroll
    for (int r = 0; r < 16; ++r)
        a[r] = sm[swz4((unsigned)(w << 9) | (r << 5) | lane)];

    // m2 gates: states 5..8 (reg)
#pragma unroll
    for (int rb = 0; rb < 4; ++rb)
        reg_gate_r(a, rb, s_gc[5 + rb], s_gs[5 + rb]);

    // post-phase for state bits 0..2 (lane bits, thread-constant) + store
    {
        float th3 = (float)(lane & 1)        * s_post[0]
                  + (float)((lane >> 1) & 1) * s_post[1]
                  + (float)((lane >> 2) & 1) * s_post[2];
        float sn3, cs3; __sincosf(th3, &sn3, &cs3);
        u64c CS = pk(cs3, cs3), SN = pk(sn3, sn3);
#pragma unroll
        for (int r = 0; r < 16; ++r)
            g_scratch[base + ((unsigned)(w << 9) | (r << 5) | lane)]
                = crot(a[r], CS, SN);
    }
}

// ---------------------------------------------------------------------------
// Pass 2 (per-state launch, p in {0,1}): l0 = b*8, 1024 blocks.
// tile bit j>=3 = state bit 10+j:
//   lane gates: tile bits 3,4 -> state 13,14
//   reg m1: tile bits 9..12 -> state 19..22
//   restage; reg m2: tile bits 5..8 -> state 15..18
// Post-phase: states 15..18 via packed 16-entry phasor table (per r);
// states 0..2 were already applied by pass1 at store (NOT repeated here);
// everything else thread-constant -> one end rotation.
// Last of ALL 2048 blocks (both launches): fixed-order reduction -> out[0].
// ---------------------------------------------------------------------------
__global__ void __launch_bounds__(512, 2)
pass2_kernel(const float* __restrict__ c1r, const float* __restrict__ c1i,
             const float* __restrict__ ur,  const float* __restrict__ ui,
             float* __restrict__ out, unsigned p)
{
    __shared__ float s_gc[23], s_gs[23], s_pre[23], s_post[23];
    __shared__ u64c  s_qt[16];     // packed (cs,sn) phasors for post 15..18
    __shared__ float red[72];
    __shared__ int   s_isLast;
    extern __shared__ u64c sm[];

    const int tid  = threadIdx.x;
    decompose(tid, ur, ui, s_gc, s_gs, s_pre, s_post);
    __syncthreads();

    if (tid < 16) {
        float ang = 0.0f;
#pragma unroll
        for (int m = 0; m < 4; ++m)
            ang += (float)((tid >> m) & 1) * s_post[15 + m];
        float sn, cs; __sincosf(ang, &sn, &cs);
        s_qt[tid] = pk(cs, sn);
    }

    const int lane = tid & 31;
    const int w    = tid >> 5;
    const unsigned b  = blockIdx.x;          // 0..1023
    const unsigned l0 = b * 8u;
    const unsigned stateBase = p << 23;

    u64c a[16];
#pragma unroll
    for (int r = 0; r < 16; ++r) {
        unsigned t1 = (unsigned)(r << 9) | (w << 5) | lane;
        unsigned s  = ((t1 >> 3) << 13) + l0 + (t1 & 7u);
        a[r] = g_scratch[stateBase + s];
    }

    // m1: lane gates state 13,14 (tile bits 3,4); reg gates states 19..22
    lane_gate_r(a, 1 << 3, (lane >> 3) & 1, s_gc[13], s_gs[13]);
    lane_gate_r(a, 1 << 4, (lane >> 4) & 1, s_gc[14], s_gs[14]);
#pragma unroll
    for (int rb = 0; rb < 4; ++rb)
        reg_gate_r(a, rb, s_gc[19 + rb], s_gs[19 + rb]);

    // restage m1 -> m2 (swap reg bits <-> warp bits); also orders s_qt
#pragma unroll
    for (int r = 0; r < 16; ++r)
        sm[(unsigned)(r << 9) | (w << 5) | lane] = a[r];
    __syncthreads();
#pragma unroll
    for (int r = 0; r < 16; ++r)
        a[r] = sm[(unsigned)(w << 9) | (r << 5) | lane];

    // m2 reg gates: states 15..18 (tile bits 5..8 = r bits)
#pragma unroll
    for (int rb = 0; rb < 4; ++rb)
        reg_gate_r(a, rb, s_gc[15 + rb], s_gs[15 + rb]);

    // fused dot with per-r packed table phasor; pipelined c1 loads.
    const unsigned sB = (((unsigned)(w << 6) | (unsigned)(lane >> 3)) << 13)
                      + l0 + (unsigned)(lane & 7);
    float acc0 = 0.f, acc1 = 0.f, acc2 = 0.f, acc3 = 0.f;
    unsigned sp = sB;
    float nxr = __ldg(&c1r[sp]),        nxi = __ldg(&c1i[sp]);
    float nyr = __ldg(&c1r[DIMQ + sp]), nyi = __ldg(&c1i[DIMQ + sp]);
#pragma unroll
    for (int r = 0; r < 16; ++r) {
        float xr = nxr, xi = nxi, yr = nyr, yi = nyi;
        if (r < 15) {
            sp += (1u << 15);
            nxr = __ldg(&c1r[sp]);        nxi = __ldg(&c1i[sp]);
            nyr = __ldg(&c1r[DIMQ + sp]); nyi = __ldg(&c1i[DIMQ + sp]);
        }
        u64c d = crotp(a[r], s_qt[r]);
        float dr, di; upk(d, dr, di);
        acc0 += dr*xr + di*xi;
        acc1 += dr*xi - di*xr;
        acc2 += dr*yr + di*yi;
        acc3 += dr*yi - di*yr;
    }

    // end rotation: thread-constant post bits EXCLUDING 0..2 (done in pass1)
    {
        float thc = 0.0f;
#pragma unroll
        for (int m = 0; m < 10; ++m)
            thc += (float)((b >> m) & 1u) * s_post[3 + m];
        thc += (float)((lane >> 3) & 1) * s_post[13];
        thc += (float)((lane >> 4) & 1) * s_post[14];
#pragma unroll
        for (int m = 0; m < 4; ++m)
            thc += (float)((w >> m) & 1) * s_post[19 + m];
        float snc, csc; __sincosf(thc, &snc, &csc);
        float n0 = acc0*csc + acc1*snc, n1 = acc1*csc - acc0*snc;
        float n2 = acc2*csc + acc3*snc, n3 = acc3*csc - acc2*snc;
        acc0 = n0; acc1 = n1; acc2 = n2; acc3 = n3;
    }

#pragma unroll
    for (int o = 16; o > 0; o >>= 1) {
        acc0 += __shfl_xor_sync(0xffffffffu, acc0, o);
        acc1 += __shfl_xor_sync(0xffffffffu, acc1, o);
        acc2 += __shfl_xor_sync(0xffffffffu, acc2, o);
        acc3 += __shfl_xor_sync(0xffffffffu, acc3, o);
    }
    if (lane == 0) {
        red[w*4+0] = acc0; red[w*4+1] = acc1;
        red[w*4+2] = acc2; red[w*4+3] = acc3;
    }
    __syncthreads();
    if (tid < 4) {
        float s = 0.f;
#pragma unroll
        for (int k = 0; k < 16; ++k) s += red[k*4 + tid];
        red[64 + tid] = s;
    }
    __syncthreads();
    const unsigned pb = (p << 10) | b;
    if (tid == 0) {
        g_partials[pb*4+0] = red[64];
        g_partials[pb*4+1] = red[65];
        g_partials[pb*4+2] = red[66];
        g_partials[pb*4+3] = red[67];
        __threadfence();
        unsigned ticket = atomicAdd(&g_count, 1u);
        s_isLast = (ticket == 2047u) ? 1 : 0;
    }
    __syncthreads();

    if (s_isLast) {
        float acc[8];
#pragma unroll
        for (int j = 0; j < 8; ++j) acc[j] = 0.f;
#pragma unroll
        for (int i = 0; i < 4; ++i) {
            unsigned bb = (unsigned)tid * 4u + i;      // 0..2047
            unsigned pq = bb >> 10;                    // state p of partial
#pragma unroll
            for (int j = 0; j < 4; ++j)
                acc[pq*4 + j] += __ldcg(&g_partials[bb*4 + j]);
        }
#pragma unroll
        for (int o = 16; o > 0; o >>= 1)
#pragma unroll
            for (int j = 0; j < 8; ++j)
                acc[j] += __shfl_xor_sync(0xffffffffu, acc[j], o);
        float* r2 = (float*)sm;
        if (lane == 0)
#pragma unroll
            for (int j = 0; j < 8; ++j) r2[w*8 + j] = acc[j];
        __syncthreads();
        if (tid < 8) {
            float s = 0.f;
#pragma unroll
            for (int k = 0; k < 16; ++k) s += r2[k*8 + tid];
            r2[128 + tid] = s;
        }
        __syncthreads();
        if (tid == 0) {
            float s = 0.f;
#pragma unroll
            for (int j = 0; j < 8; ++j) s += r2[128 + j] * r2[128 + j];
            out[0] = 2.0f - s;
            g_count = 0;               // reset for next graph replay
        }
    }
}

// ---------------------------------------------------------------------------
// Fork-join schedule (graph-capturable):
//   legacy: pass1(h0) -> e0 -> pass1(h1) -> e1
//   s2:     wait(e0) -> pass2(p0) -> wait(e1) -> pass2(p1) -> e2
//   legacy: wait(e2)
// pass2(p0) reads scratch half 0 only; runs concurrent with pass1(h1).
// ---------------------------------------------------------------------------
extern "C" void kernel_launch(void* const* d_in, const int* in_sizes, int n_in,
                              void* d_out, int out_size)
{
    (void)in_sizes; (void)n_in; (void)out_size;
    const float* c0r = (const float*)d_in[0];
    const float* c0i = (const float*)d_in[1];
    const float* c1r = (const float*)d_in[2];
    const float* c1i = (const float*)d_in[3];
    const float* ur  = (const float*)d_in[4];
    const float* ui  = (const float*)d_in[5];
    float* out = (float*)d_out;

    cudaFuncSetAttribute(pass1_kernel, cudaFuncAttributeMaxDynamicSharedMemorySize, 65536);
    cudaFuncSetAttribute(pass2_kernel, cudaFuncAttributeMaxDynamicSharedMemorySize, 65536);

    cudaStream_t s2;
    cudaEvent_t  e0, e1, e2;
    cudaStreamCreateWithFlags(&s2, cudaStreamNonBlocking);
    cudaEventCreateWithFlags(&e0, cudaEventDisableTiming);
    cudaEventCreateWithFlags(&e1, cudaEventDisableTiming);
    cudaEventCreateWithFlags(&e2, cudaEventDisableTiming);

    pass1_kernel<<<1024, 512, 65536>>>(c0r, c0i, ur, ui, 0u);
    cudaEventRecord(e0, 0);
    cudaStreamWaitEvent(s2, e0, 0);
    pass2_kernel<<<1024, 512, 65536, s2>>>(c1r, c1i, ur, ui, out, 0u);

    pass1_kernel<<<1024, 512, 65536>>>(c0r, c0i, ur, ui, 1024u);
    cudaEventRecord(e1, 0);
    cudaStreamWaitEvent(s2, e1, 0);
    pass2_kernel<<<1024, 512, 65536, s2>>>(c1r, c1i, ur, ui, out, 1u);

    cudaEventRecord(e2, s2);
    cudaStreamWaitEvent((cudaStream_t)0, e2, 0);
    // streams/events intentionally not destroyed: kernel_launch is only
    // invoked for the correctness run and graph capture, and destroying a
    // forked stream mid-capture would invalidate the capture.
}

// round 15
// speedup vs baseline: 1.0918x; 1.0918x over previous
#include <cuda_runtime.h>
#include <math.h>

// ---------------------------------------------------------------------------
// QECCEqualModel via Givens decomposition (M_k = D1*G*D2):
//   D2 bits 9..12  -> 16-entry phasor table at pass1 load
//   D2 all other   -> one thread-constant rotation at pass1 load
//   G              -> real Givens rotations
//   D1 bits 0..2   -> thread-constant rotation at pass1 store (ONLY here)
//   D1 bits 15..18 -> 16-entry packed phasor table in pass2 dot
//   D1 all other   -> single thread-constant end rotation in pass2
// pass1: G on state bits 0..12 via THREE register mappings (2 restages,
//        only ONE shfl gate), contiguous tiles -> scratch.
// pass2: G on state bits 13..22 (gathered), fused dot with code1,
//        p = b&1 twin-sharing of c1 in L2, last-block reduction -> loss.
// Two launches total.
// ---------------------------------------------------------------------------

#define DIMQ (1u << 23)
typedef unsigned long long u64c;

__device__ u64c     g_scratch[2u * DIMQ];
__device__ float    g_partials[2048 * 4];
__device__ unsigned g_count;               // zero-init; reset by last block

__device__ __forceinline__ u64c pk(float x, float y) {
    u64c r; asm("mov.b64 %0,{%1,%2};" : "=l"(r) : "f"(x), "f"(y)); return r;
}
__device__ __forceinline__ void upk(u64c a, float& x, float& y) {
    asm("mov.b64 {%0,%1},%2;" : "=f"(x), "=f"(y) : "l"(a));
}
__device__ __forceinline__ u64c fma2(u64c a, u64c b, u64c c) {
    u64c r; asm("fma.rn.f32x2 %0,%1,%2,%3;" : "=l"(r) : "l"(a), "l"(b), "l"(c)); return r;
}
__device__ __forceinline__ u64c mul2(u64c a, u64c b) {
    u64c r; asm("mul.rn.f32x2 %0,%1,%2;" : "=l"(r) : "l"(a), "l"(b)); return r;
}
// rotate packed complex a by phasor (cs,sn): (x cs - y sn, y cs + x sn)
__device__ __forceinline__ u64c crot(u64c a, u64c CS, u64c SN) {
    float x, y; upk(a, x, y);
    return fma2(pk(-y, x), SN, mul2(a, CS));
}
// rotate by packed phasor (cs,sn) held in one u64
__device__ __forceinline__ u64c crotp(u64c a, u64c P) {
    float cs, sn; upk(P, cs, sn);
    float x, y; upk(a, x, y);
    return fma2(pk(-y, x), pk(sn, sn), mul2(a, pk(cs, cs)));
}

__device__ __forceinline__ unsigned swz4(unsigned i) { return i ^ ((i >> 4) & 0xFu); }

// Per-block Givens decomposition of all 23 gates into smem (threads 0..22).
// M = U^T = [[c e^{ia}, -s e^{i(a+d)}],[s e^{ib}, c e^{i(b+d)}]]
__device__ __forceinline__ void decompose(
    int tid, const float* __restrict__ ur, const float* __restrict__ ui,
    float* s_gc, float* s_gs, float* s_pre, float* s_post)
{
    if (tid < 23) {
        int k = tid;
        float m00r = ur[k*4+0], m00i = ui[k*4+0];
        float m01r = ur[k*4+2], m01i = ui[k*4+2];
        float m10r = ur[k*4+1], m10i = ui[k*4+1];
        float m11r = ur[k*4+3], m11i = ui[k*4+3];
        float c = sqrtf(m00r*m00r + m00i*m00i);
        float s = sqrtf(m10r*m10r + m10i*m10i);
        const float eps = 1e-20f;
        float a = (c > eps) ? atan2f(m00i, m00r) : 0.0f;
        float b = (s > eps) ? atan2f(m10i, m10r) : 0.0f;
        float d = (s > eps) ? (atan2f(-m01i, -m01r) - a)
                            : (atan2f(m11i, m11r) - b);
        int j = 22 - k;            // gate k acts on state bit 22-k
        s_gc[j] = c; s_gs[j] = s;
        s_pre[j] = d; s_post[j] = b - a;
    }
}

// Real Givens across a register bit rb: o0 = c*A0 - s*A1 ; o1 = s*A0 + c*A1
__device__ __forceinline__ void reg_gate_r(u64c (&a)[16], int rb, float c, float s)
{
    u64c cc = pk(c, c), ss = pk(s, s), ns = pk(-s, -s);
#pragma unroll
    for (int r0 = 0; r0 < 16; ++r0) {
        if (r0 & (1 << rb)) continue;
        int r1 = r0 | (1 << rb);
        u64c A0 = a[r0], A1 = a[r1];
        a[r0] = fma2(A1, ns, mul2(A0, cc));
        a[r1] = fma2(A1, cc, mul2(A0, ss));
    }
}

// Real Givens across a lane bit: new = c*me + t*other, t = myb ? s : -s
__device__ __forceinline__ void lane_gate_r(u64c (&a)[16], int mask, int myb,
                                            float c, float s)
{
    float t = myb ? s : -s;
    u64c cc = pk(c, c), tt = pk(t, t);
#pragma unroll
    for (int r = 0; r < 16; ++r) {
        float mx, my; upk(a[r], mx, my);
        float ox = __shfl_xor_sync(0xffffffffu, mx, mask);
        float oy = __shfl_xor_sync(0xffffffffu, my, mask);
        a[r] = fma2(pk(ox, oy), tt, mul2(a[r], cc));
    }
}

// ---------------------------------------------------------------------------
// Pass 1: contiguous tiles of 8192 amps; three mappings, ONE shfl gate.
// m1   t1 = (r<<9)|(w<<5)|lane : lane = tile 0..4, warp = 5..8, reg = 9..12
//        -> gates: reg states 9..12, shfl state 4. Pre-phase at load.
// mmid t  = (w<<9)|(lane<<4)|r : reg = tile 0..3  -> gates states 0..3
// m2   t2 = (w<<9)|(r<<5)|lane : reg = tile 5..8  -> gates states 5..8
//        -> post-phase bits 0..2 (lane-const) + coalesced store.
// Restages use swizzle swz4 (<=2-way conflicts).
// ---------------------------------------------------------------------------
__global__ void __launch_bounds__(512, 2)
pass1_kernel(const float* __restrict__ c0r, const float* __restrict__ c0i,
             const float* __restrict__ ur,  const float* __restrict__ ui)
{
    __shared__ float s_gc[23], s_gs[23], s_pre[23], s_post[23];
    __shared__ u64c  s_pt[16];     // packed (cs,sn) phasors for pre bits 9..12
    extern __shared__ u64c sm[];   // 8192 u64 = 64 KB restage buffer

    const int tid  = threadIdx.x;
    decompose(tid, ur, ui, s_gc, s_gs, s_pre, s_post);
    __syncthreads();

    if (tid < 16) {
        float ang = 0.0f;
#pragma unroll
        for (int m = 0; m < 4; ++m)
            ang += (float)((tid >> m) & 1) * s_pre[9 + m];
        float sn, cs; __sincosf(ang, &sn, &cs);
        s_pt[tid] = pk(cs, sn);
    }
    __syncthreads();

    const int lane = tid & 31;
    const int w    = tid >> 5;
    const unsigned bid  = blockIdx.x;
    const unsigned base = bid * 8192u;

    // thread-constant pre-phase (bid bits 0..9 = state bits 13..22)
    float th = 0.0f;
#pragma unroll
    for (int m = 0; m < 10; ++m)
        th += (float)((bid >> m) & 1u) * s_pre[13 + m];
#pragma unroll
    for (int j = 0; j < 5; ++j)
        th += (float)((lane >> j) & 1) * s_pre[j];
#pragma unroll
    for (int m = 0; m < 4; ++m)
        th += (float)((w >> m) & 1) * s_pre[5 + m];
    float snT, csT; __sincosf(th, &snT, &csT);
    const u64c TC = pk(csT, csT), TS = pk(snT, snT);

    u64c a[16];
#pragma unroll
    for (int r = 0; r < 16; ++r) {
        unsigned t1 = (unsigned)(r << 9) | (w << 5) | lane;
        float xr = __ldg(&c0r[base + t1]);
        float xi = __ldg(&c0i[base + t1]);
        u64c x = crotp(pk(xr, xi), s_pt[r]);
        a[r] = crot(x, TC, TS);
    }

    // m1 gates: states 9..12 (reg), state 4 (shfl)
#pragma unroll
    for (int rb = 0; rb < 4; ++rb)
        reg_gate_r(a, rb, s_gc[9 + rb], s_gs[9 + rb]);
    lane_gate_r(a, 1 << 4, (lane >> 4) & 1, s_gc[4], s_gs[4]);

    // restage A: m1 -> mmid
#pragma unroll
    for (int r = 0; r < 16; ++r)
        sm[swz4((unsigned)(r << 9) | (w << 5) | lane)] = a[r];
    __syncthreads();
#pragma unroll
    for (int r = 0; r < 16; ++r)
        a[r] = sm[swz4((unsigned)(w << 9) | (lane << 4) | r)];

    // mmid gates: states 0..3 (reg)
#pragma unroll
    for (int rb = 0; rb < 4; ++rb)
        reg_gate_r(a, rb, s_gc[rb], s_gs[rb]);

    __syncthreads();   // everyone done reading restage A data
    // restage B: mmid -> m2
#pragma unroll
    for (int r = 0; r < 16; ++r)
        sm[swz4((unsigned)(w << 9) | (lane << 4) | r)] = a[r];
    __syncthreads();
#pragma unroll
    for (int r = 0; r < 16; ++r)
        a[r] = sm[swz4((unsigned)(w << 9) | (r << 5) | lane)];

    // m2 gates: states 5..8 (reg)
#pragma unroll
    for (int rb = 0; rb < 4; ++rb)
        reg_gate_r(a, rb, s_gc[5 + rb], s_gs[5 + rb]);

    // post-phase for state bits 0..2 (lane bits, thread-constant) + store
    {
        float th3 = (float)(lane & 1)        * s_post[0]
                  + (float)((lane >> 1) & 1) * s_post[1]
                  + (float)((lane >> 2) & 1) * s_post[2];
        float sn3, cs3; __sincosf(th3, &sn3, &cs3);
        u64c CS = pk(cs3, cs3), SN = pk(sn3, sn3);
#pragma unroll
        for (int r = 0; r < 16; ++r)
            g_scratch[base + ((unsigned)(w << 9) | (r << 5) | lane)]
                = crot(a[r], CS, SN);
    }
}

// ---------------------------------------------------------------------------
// Pass 2: p = b&1 (L2 twin-sharing of c1), l0 = (b>>1)*8, 2048 blocks.
// Gathered tiles (2^10 high combos x 8 contiguous low), fused dot.
// tile bit j>=3 = state bit 10+j:
//   lane gates: tile bits 3,4 -> state 13,14
//   reg m1: tile bits 9..12 -> state 19..22
//   restage; reg m2: tile bits 5..8 -> state 15..18
// Post-phase: states 15..18 via packed 16-entry phasor table (per r);
// states 0..2 already applied by pass1 at store (NOT repeated here);
// everything else thread-constant -> one end rotation.
// Last block: deterministic fixed-order reduction -> out[0].
// ---------------------------------------------------------------------------
__global__ void __launch_bounds__(512, 2)
pass2_kernel(const float* __restrict__ c1r, const float* __restrict__ c1i,
             const float* __restrict__ ur,  const float* __restrict__ ui,
             float* __restrict__ out)
{
    __shared__ float s_gc[23], s_gs[23], s_pre[23], s_post[23];
    __shared__ u64c  s_qt[16];     // packed (cs,sn) phasors for post 15..18
    __shared__ float red[72];
    __shared__ int   s_isLast;
    extern __shared__ u64c sm[];

    const int tid  = threadIdx.x;
    decompose(tid, ur, ui, s_gc, s_gs, s_pre, s_post);
    __syncthreads();

    if (tid < 16) {
        float ang = 0.0f;
#pragma unroll
        for (int m = 0; m < 4; ++m)
            ang += (float)((tid >> m) & 1) * s_post[15 + m];
        float sn, cs; __sincosf(ang, &sn, &cs);
        s_qt[tid] = pk(cs, sn);
    }

    const int lane = tid & 31;
    const int w    = tid >> 5;
    const unsigned b  = blockIdx.x;
    const unsigned p  = b & 1u;
    const unsigned l0 = (b >> 1) * 8u;
    const unsigned stateBase = p << 23;

    u64c a[16];
#pragma unroll
    for (int r = 0; r < 16; ++r) {
        unsigned t1 = (unsigned)(r << 9) | (w << 5) | lane;
        unsigned s  = ((t1 >> 3) << 13) + l0 + (t1 & 7u);
        a[r] = g_scratch[stateBase + s];
    }

    // m1: lane gates state 13,14 (tile bits 3,4); reg gates states 19..22
    lane_gate_r(a, 1 << 3, (lane >> 3) & 1, s_gc[13], s_gs[13]);
    lane_gate_r(a, 1 << 4, (lane >> 4) & 1, s_gc[14], s_gs[14]);
#pragma unroll
    for (int rb = 0; rb < 4; ++rb)
        reg_gate_r(a, rb, s_gc[19 + rb], s_gs[19 + rb]);

    // restage m1 -> m2 (swap reg bits <-> warp bits); also orders s_qt
#pragma unroll
    for (int r = 0; r < 16; ++r)
        sm[(unsigned)(r << 9) | (w << 5) | lane] = a[r];
    __syncthreads();
#pragma unroll
    for (int r = 0; r < 16; ++r)
        a[r] = sm[(unsigned)(w << 9) | (r << 5) | lane];

    // m2 reg gates: states 15..18 (tile bits 5..8 = r bits)
#pragma unroll
    for (int rb = 0; rb < 4; ++rb)
        reg_gate_r(a, rb, s_gc[15 + rb], s_gs[15 + rb]);

    // fused dot with per-r packed table phasor; pipelined c1 loads.
    // s(r) = base + r * 2^15  (t2 = (w<<9)|(r<<5)|lane)
    const unsigned sB = (((unsigned)(w << 6) | (unsigned)(lane >> 3)) << 13)
                      + l0 + (unsigned)(lane & 7);
    float acc0 = 0.f, acc1 = 0.f, acc2 = 0.f, acc3 = 0.f;
    unsigned sp = sB;
    float nxr = __ldg(&c1r[sp]),        nxi = __ldg(&c1i[sp]);
    float nyr = __ldg(&c1r[DIMQ + sp]), nyi = __ldg(&c1i[DIMQ + sp]);
#pragma unroll
    for (int r = 0; r < 16; ++r) {
        float xr = nxr, xi = nxi, yr = nyr, yi = nyi;
        if (r < 15) {
            sp += (1u << 15);
            nxr = __ldg(&c1r[sp]);        nxi = __ldg(&c1i[sp]);
            nyr = __ldg(&c1r[DIMQ + sp]); nyi = __ldg(&c1i[DIMQ + sp]);
        }
        u64c d = crotp(a[r], s_qt[r]);
        float dr, di; upk(d, dr, di);
        acc0 += dr*xr + di*xi;
        acc1 += dr*xi - di*xr;
        acc2 += dr*yr + di*yi;
        acc3 += dr*yi - di*yr;
    }

    // end rotation: thread-constant post bits EXCLUDING 0..2 (done in pass1)
    {
        float thc = 0.0f;
#pragma unroll
        for (int m = 0; m < 10; ++m)
            thc += (float)((b >> (1 + m)) & 1u) * s_post[3 + m];
        thc += (float)((lane >> 3) & 1) * s_post[13];
        thc += (float)((lane >> 4) & 1) * s_post[14];
#pragma unroll
        for (int m = 0; m < 4; ++m)
            thc += (float)((w >> m) & 1) * s_post[19 + m];
        float snc, csc; __sincosf(thc, &snc, &csc);
        float n0 = acc0*csc + acc1*snc, n1 = acc1*csc - acc0*snc;
        float n2 = acc2*csc + acc3*snc, n3 = acc3*csc - acc2*snc;
        acc0 = n0; acc1 = n1; acc2 = n2; acc3 = n3;
    }

#pragma unroll
    for (int o = 16; o > 0; o >>= 1) {
        acc0 += __shfl_xor_sync(0xffffffffu, acc0, o);
        acc1 += __shfl_xor_sync(0xffffffffu, acc1, o);
        acc2 += __shfl_xor_sync(0xffffffffu, acc2, o);
        acc3 += __shfl_xor_sync(0xffffffffu, acc3, o);
    }
    if (lane == 0) {
        red[w*4+0] = acc0; red[w*4+1] = acc1;
        red[w*4+2] = acc2; red[w*4+3] = acc3;
    }
    __syncthreads();
    if (tid < 4) {
        float s = 0.f;
#pragma unroll
        for (int k = 0; k < 16; ++k) s += red[k*4 + tid];
        red[64 + tid] = s;
    }
    __syncthreads();
    if (tid == 0) {
        g_partials[b*4+0] = red[64];
        g_partials[b*4+1] = red[65];
        g_partials[b*4+2] = red[66];
        g_partials[b*4+3] = red[67];
        __threadfence();
        unsigned ticket = atomicAdd(&g_count, 1u);
        s_isLast = (ticket == gridDim.x - 1u) ? 1 : 0;
    }
    __syncthreads();

    if (s_isLast) {
        float acc[8];
#pragma unroll
        for (int j = 0; j < 8; ++j) acc[j] = 0.f;
#pragma unroll
        for (int i = 0; i < 4; ++i) {
            unsigned bb = (unsigned)tid * 4u + i;
            unsigned pq = bb & 1u;
#pragma unroll
            for (int j = 0; j < 4; ++j)
                acc[pq*4 + j] += __ldcg(&g_partials[bb*4 + j]);
        }
#pragma unroll
        for (int o = 16; o > 0; o >>= 1)
#pragma unroll
            for (int j = 0; j < 8; ++j)
                acc[j] += __shfl_xor_sync(0xffffffffu, acc[j], o);
        float* r2 = (float*)sm;
        if (lane == 0)
#pragma unroll
            for (int j = 0; j < 8; ++j) r2[w*8 + j] = acc[j];
        __syncthreads();
        if (tid < 8) {
            float s = 0.f;
#pragma unroll
            for (int k = 0; k < 16; ++k) s += r2[k*8 + tid];
            r2[128 + tid] = s;
        }
        __syncthreads();
        if (tid == 0) {
            float s = 0.f;
#pragma unroll
            for (int j = 0; j < 8; ++j) s += r2[128 + j] * r2[128 + j];
            out[0] = 2.0f - s;
            g_count = 0;               // reset for next graph replay
        }
    }
}

// ---------------------------------------------------------------------------
extern "C" void kernel_launch(void* const* d_in, const int* in_sizes, int n_in,
                              void* d_out, int out_size)
{
    (void)in_sizes; (void)n_in; (void)out_size;
    const float* c0r = (const float*)d_in[0];
    const float* c0i = (const float*)d_in[1];
    const float* c1r = (const float*)d_in[2];
    const float* c1i = (const float*)d_in[3];
    const float* ur  = (const float*)d_in[4];
    const float* ui  = (const float*)d_in[5];

    cudaFuncSetAttribute(pass1_kernel, cudaFuncAttributeMaxDynamicSharedMemorySize, 65536);
    cudaFuncSetAttribute(pass2_kernel, cudaFuncAttributeMaxDynamicSharedMemorySize, 65536);

    pass1_kernel<<<2048, 512, 65536>>>(c0r, c0i, ur, ui);
    pass2_kernel<<<2048, 512, 65536>>>(c1r, c1i, ur, ui, (float*)d_out);
}